// round 11
// baseline (speedup 1.0000x reference)
#include <cuda_runtime.h>
#include <cstdint>

// ===================== problem constants =====================
static constexpr int MROWS = 32768;
static constexpr int KDIM  = 1024;
static constexpr int NDIM  = 1024;

// ===================== GEMM tiling =====================
static constexpr int BM = 128;
static constexpr int BN = 128;
static constexpr int BK = 64;                 // int8 k per tile
static constexpr int KTILES = KDIM / BK;      // 16
static constexpr int NSTAGE = 3;
static constexpr int PITCH = 80;              // 64B data + 16B pad (conflict-free)
static constexpr int TILE_BYTES = 128 * PITCH;          // 10240 per operand
static constexpr int STAGE_BYTES = 2 * TILE_BYTES;      // A + B
static constexpr int SMEM_BYTES = NSTAGE * STAGE_BYTES; // 61440

// ===================== scratch =====================
__device__ __align__(16) int8_t g_q[(size_t)MROWS * KDIM];   // int8 activations (32MB)
__device__ __align__(16) int8_t g_w[(size_t)NDIM * KDIM];    // int8 weights [N,K] (1MB)

// ===================== helpers =====================
__device__ __forceinline__ uint32_t smem_u32(const void* p) {
    uint32_t a;
    asm("{ .reg .u64 t; cvta.to.shared.u64 t, %1; cvt.u32.u64 %0, t; }" : "=r"(a) : "l"(p));
    return a;
}
__device__ __forceinline__ void cp_async16(uint32_t dst, const void* src) {
    asm volatile("cp.async.cg.shared.global [%0], [%1], 16;" :: "r"(dst), "l"(src) : "memory");
}
__device__ __forceinline__ void cp_commit() {
    asm volatile("cp.async.commit_group;" ::: "memory");
}
template <int N>
__device__ __forceinline__ void cp_wait() {
    asm volatile("cp.async.wait_group %0;" :: "n"(N) : "memory");
}
__device__ __forceinline__ uint32_t lds32(uint32_t addr) {
    uint32_t v;
    asm volatile("ld.shared.b32 %0, [%1];" : "=r"(v) : "r"(addr));
    return v;
}
__device__ __forceinline__ void mma_s8(int* d, const uint32_t* a, const uint32_t* b) {
    asm volatile(
        "mma.sync.aligned.m16n8k32.row.col.s32.s8.s8.s32 "
        "{%0,%1,%2,%3}, {%4,%5,%6,%7}, {%8,%9}, {%0,%1,%2,%3};"
        : "+r"(d[0]), "+r"(d[1]), "+r"(d[2]), "+r"(d[3])
        : "r"(a[0]), "r"(a[1]), "r"(a[2]), "r"(a[3]), "r"(b[0]), "r"(b[1]));
}

// ===================== pass 1: quantize fp32 -> int8 =====================
__global__ void __launch_bounds__(256) quant_kernel(const float* __restrict__ x) {
    int i = blockIdx.x * blockDim.x + threadIdx.x;
    if (i >= MROWS * KDIM) return;
    float q = rintf(__fmul_rn(x[i], 20.0f));        // RNE, matches jnp.round
    q = fmaxf(-127.0f, fminf(127.0f, q));
    g_q[i] = (int8_t)(int)q;
}

// ===================== pass 1b: unpack int4 -> int8 =====================
// KEY FIX: weight_packed is delivered as int32 elements (uint8 widened by the
// harness). One int32 element == one packed byte in its low 8 bits.
// element i -> g_w[2i] = signed low nibble, g_w[2i+1] = signed high nibble
__global__ void __launch_bounds__(256) unpack_kernel(const int* __restrict__ wp) {
    int i = blockIdx.x * blockDim.x + threadIdx.x;
    if (i >= (NDIM * KDIM) / 2) return;
    int b = wp[i] & 0xFF;
    int lo = (b & 0xF);       lo -= (lo >= 8) ? 16 : 0;
    int hi = (b >> 4) & 0xF;  hi -= (hi >= 8) ? 16 : 0;
    g_w[2 * i]     = (int8_t)lo;
    g_w[2 * i + 1] = (int8_t)hi;
}

// ===================== pass 2: IMMA GEMM (bit-identical to R8) =====================
__global__ void __launch_bounds__(128, 2)
gemm_kernel(const float* __restrict__ bias, float* __restrict__ out) {
    extern __shared__ char smem[];
    const uint32_t sbase = smem_u32(smem);
    const int tid  = threadIdx.x;
    const int wid  = tid >> 5;
    const int lane = tid & 31;
    const int g = lane >> 2, t = lane & 3;
    const int wm = (wid & 1) * 64;
    const int wn = (wid >> 1) * 64;
    const int n0 = blockIdx.x * BN;
    const int m0 = blockIdx.y * BM;

    const int8_t* gA = g_q + (size_t)m0 * KDIM;
    const int8_t* gB = g_w + (size_t)n0 * KDIM;

    auto load_stage = [&](int s, int kt) {
        const uint32_t sa = sbase + s * STAGE_BYTES;
        const uint32_t sb = sa + TILE_BYTES;
        const int kb = kt * BK;
#pragma unroll
        for (int it = 0; it < 4; it++) {
            int c = tid + it * 128;
            int row = c >> 2, col = c & 3;
            cp_async16(sa + row * PITCH + col * 16,
                       gA + (size_t)row * KDIM + kb + col * 16);
        }
#pragma unroll
        for (int it = 0; it < 4; it++) {
            int c = tid + it * 128;
            int row = c >> 2, col = c & 3;
            cp_async16(sb + row * PITCH + col * 16,
                       gB + (size_t)row * KDIM + kb + col * 16);
        }
    };

    int acc[4][8][4];
#pragma unroll
    for (int mi = 0; mi < 4; mi++)
#pragma unroll
        for (int ni = 0; ni < 8; ni++)
#pragma unroll
            for (int r = 0; r < 4; r++) acc[mi][ni][r] = 0;

    load_stage(0, 0); cp_commit();
    load_stage(1, 1); cp_commit();

#pragma unroll 1
    for (int kt = 0; kt < KTILES; kt++) {
        if (kt + 2 < KTILES) load_stage((kt + 2) % NSTAGE, kt + 2);
        cp_commit();
        cp_wait<2>();
        __syncthreads();

        const uint32_t sa = sbase + (kt % NSTAGE) * STAGE_BYTES;
        const uint32_t sb = sa + TILE_BYTES;

#pragma unroll
        for (int c = 0; c < 2; c++) {
            const int kof = c * 32 + 4 * t;
            uint32_t afr[4][4];
#pragma unroll
            for (int mi = 0; mi < 4; mi++) {
                uint32_t base = sa + (wm + mi * 16 + g) * PITCH + kof;
                afr[mi][0] = lds32(base);
                afr[mi][1] = lds32(base + 8 * PITCH);
                afr[mi][2] = lds32(base + 16);
                afr[mi][3] = lds32(base + 8 * PITCH + 16);
            }
            uint32_t bfr[8][2];
#pragma unroll
            for (int ni = 0; ni < 8; ni++) {
                uint32_t bb = sb + (wn + ni * 8 + g) * PITCH + kof;
                bfr[ni][0] = lds32(bb);
                bfr[ni][1] = lds32(bb + 16);
            }
#pragma unroll
            for (int mi = 0; mi < 4; mi++)
#pragma unroll
                for (int ni = 0; ni < 8; ni++)
                    mma_s8(acc[mi][ni], afr[mi], bfr[ni]);
        }
        __syncthreads();
    }

    // ---- epilogue: out = acc * (A_SCALE * W_SCALE) + bias, FP32 ----
    const float SCALE = 5.0e-4f;
#pragma unroll
    for (int mi = 0; mi < 4; mi++) {
        const int row = m0 + wm + mi * 16 + g;
        float* p0 = out + (size_t)row * NDIM + n0 + wn;
        float* p1 = p0 + (size_t)8 * NDIM;
#pragma unroll
        for (int ni = 0; ni < 8; ni++) {
            const int* cc = acc[mi][ni];
            const int coff = ni * 8 + t * 2;
            float b0 = bias[n0 + wn + coff];
            float b1 = bias[n0 + wn + coff + 1];
            float2 v01, v23;
            v01.x = __fadd_rn(__fmul_rn((float)cc[0], SCALE), b0);
            v01.y = __fadd_rn(__fmul_rn((float)cc[1], SCALE), b1);
            v23.x = __fadd_rn(__fmul_rn((float)cc[2], SCALE), b0);
            v23.y = __fadd_rn(__fmul_rn((float)cc[3], SCALE), b1);
            *(float2*)(p0 + coff) = v01;
            *(float2*)(p1 + coff) = v23;
        }
    }
}

// ===================== launch =====================
extern "C" void kernel_launch(void* const* d_in, const int* in_sizes, int n_in,
                              void* d_out, int out_size) {
    const float* x    = nullptr;
    const int*   wp   = nullptr;
    const float* bias = nullptr;
    for (int i = 0; i < n_in; i++) {
        if (in_sizes[i] == MROWS * KDIM)            x    = (const float*)d_in[i];
        else if (in_sizes[i] == NDIM * KDIM / 2)    wp   = (const int*)d_in[i];
        else if (in_sizes[i] == NDIM)               bias = (const float*)d_in[i];
    }
    if (x == nullptr)    x    = (const float*)d_in[0];
    if (wp == nullptr)   wp   = (const int*)d_in[1];
    if (bias == nullptr) bias = (const float*)d_in[2];
    float* out = (float*)d_out;

    quant_kernel<<<(MROWS * KDIM) / 256, 256>>>(x);
    unpack_kernel<<<(NDIM * KDIM / 2) / 256, 256>>>(wp);

    cudaFuncSetAttribute(gemm_kernel, cudaFuncAttributeMaxDynamicSharedMemorySize, SMEM_BYTES);
    dim3 grid(NDIM / BN, MROWS / BM);   // (8, 256)
    gemm_kernel<<<grid, 128, SMEM_BYTES>>>(bias, out);
}

// round 12
// speedup vs baseline: 1.1565x; 1.1565x over previous
#include <cuda_runtime.h>
#include <cstdint>

// ===================== problem constants =====================
static constexpr int MROWS = 32768;
static constexpr int KDIM  = 1024;
static constexpr int NDIM  = 1024;

// ===================== GEMM tiling =====================
static constexpr int BM = 128;
static constexpr int BN = 128;
static constexpr int BK = 64;                 // int8 k per tile
static constexpr int KTILES = KDIM / BK;      // 16
static constexpr int NSTAGE = 3;
static constexpr int PITCH = 80;              // 64B data + 16B pad (conflict-free)
static constexpr int TILE_BYTES = 128 * PITCH;          // 10240 per operand
static constexpr int STAGE_BYTES = 2 * TILE_BYTES;      // A + B
static constexpr int SMEM_BYTES = NSTAGE * STAGE_BYTES; // 61440

// ===================== scratch =====================
__device__ __align__(16) int8_t g_q[(size_t)MROWS * KDIM];   // int8 activations (32MB)
__device__ __align__(16) int8_t g_w[(size_t)NDIM * KDIM];    // int8 weights [N,K] (1MB)

// ===================== helpers =====================
__device__ __forceinline__ uint32_t smem_u32(const void* p) {
    uint32_t a;
    asm("{ .reg .u64 t; cvta.to.shared.u64 t, %1; cvt.u32.u64 %0, t; }" : "=r"(a) : "l"(p));
    return a;
}
__device__ __forceinline__ void cp_async16(uint32_t dst, const void* src) {
    asm volatile("cp.async.cg.shared.global [%0], [%1], 16;" :: "r"(dst), "l"(src) : "memory");
}
__device__ __forceinline__ void cp_commit() {
    asm volatile("cp.async.commit_group;" ::: "memory");
}
template <int N>
__device__ __forceinline__ void cp_wait() {
    asm volatile("cp.async.wait_group %0;" :: "n"(N) : "memory");
}
__device__ __forceinline__ void ldsm_x4(uint32_t* r, uint32_t addr) {
    asm volatile("ldmatrix.sync.aligned.m8n8.x4.shared.b16 {%0,%1,%2,%3}, [%4];"
                 : "=r"(r[0]), "=r"(r[1]), "=r"(r[2]), "=r"(r[3]) : "r"(addr));
}
__device__ __forceinline__ void mma_s8(int* d, const uint32_t* a, const uint32_t* b) {
    asm volatile(
        "mma.sync.aligned.m16n8k32.row.col.s32.s8.s8.s32 "
        "{%0,%1,%2,%3}, {%4,%5,%6,%7}, {%8,%9}, {%0,%1,%2,%3};"
        : "+r"(d[0]), "+r"(d[1]), "+r"(d[2]), "+r"(d[3])
        : "r"(a[0]), "r"(a[1]), "r"(a[2]), "r"(a[3]), "r"(b[0]), "r"(b[1]));
}

// ===================== pass 1: quantize fp32 -> int8 (vectorized 16/thread) =====================
__global__ void __launch_bounds__(256) quant_kernel(const float* __restrict__ x) {
    const int i = blockIdx.x * blockDim.x + threadIdx.x;   // one 16-element group
    const int ngroups = (MROWS * KDIM) / 16;
    if (i >= ngroups) return;
    const float4* xv = (const float4*)x + i * 4;
    uint32_t w[4];
#pragma unroll
    for (int j = 0; j < 4; j++) {
        float4 v = xv[j];
        int q0 = __float2int_rn(__fmul_rn(v.x, 20.0f));
        int q1 = __float2int_rn(__fmul_rn(v.y, 20.0f));
        int q2 = __float2int_rn(__fmul_rn(v.z, 20.0f));
        int q3 = __float2int_rn(__fmul_rn(v.w, 20.0f));
        q0 = max(-127, min(127, q0));
        q1 = max(-127, min(127, q1));
        q2 = max(-127, min(127, q2));
        q3 = max(-127, min(127, q3));
        w[j] = (uint32_t)(q0 & 0xFF) | ((uint32_t)(q1 & 0xFF) << 8) |
               ((uint32_t)(q2 & 0xFF) << 16) | ((uint32_t)(q3 & 0xFF) << 24);
    }
    uint4 st; st.x = w[0]; st.y = w[1]; st.z = w[2]; st.w = w[3];
    ((uint4*)g_q)[i] = st;
}

// ===================== pass 1b: unpack int4 -> int8 =====================
// weight_packed delivered as int32 elements (uint8 widened by harness).
// element i (4 per thread) -> g_w[2i] = signed low nibble, g_w[2i+1] = high.
__global__ void __launch_bounds__(256) unpack_kernel(const int4* __restrict__ wp) {
    int i = blockIdx.x * blockDim.x + threadIdx.x;   // one int4 = 4 packed bytes = 8 weights
    if (i >= (NDIM * KDIM) / 8) return;
    int4 e = wp[i];
    int b[4] = {e.x & 0xFF, e.y & 0xFF, e.z & 0xFF, e.w & 0xFF};
    uint2 st;
    uint32_t lohalf = 0, hihalf = 0;
#pragma unroll
    for (int j = 0; j < 2; j++) {
        int lo0 = (b[j] & 0xF);        lo0 -= (lo0 >= 8) ? 16 : 0;
        int hi0 = (b[j] >> 4) & 0xF;   hi0 -= (hi0 >= 8) ? 16 : 0;
        lohalf |= ((uint32_t)(lo0 & 0xFF) << (16 * j)) | ((uint32_t)(hi0 & 0xFF) << (16 * j + 8));
        int lo1 = (b[j + 2] & 0xF);      lo1 -= (lo1 >= 8) ? 16 : 0;
        int hi1 = (b[j + 2] >> 4) & 0xF; hi1 -= (hi1 >= 8) ? 16 : 0;
        hihalf |= ((uint32_t)(lo1 & 0xFF) << (16 * j)) | ((uint32_t)(hi1 & 0xFF) << (16 * j + 8));
    }
    st.x = lohalf; st.y = hihalf;
    ((uint2*)g_w)[i] = st;
}

// ===================== pass 2: IMMA GEMM, ldmatrix fragments =====================
// CTA: 256 threads = 8 warps in 2(m) x 4(n); warp tile 64x32.
__global__ void __launch_bounds__(256, 2)
gemm_kernel(const float* __restrict__ bias, float* __restrict__ out) {
    extern __shared__ char smem[];
    const uint32_t sbase = smem_u32(smem);
    const int tid  = threadIdx.x;
    const int wid  = tid >> 5;
    const int lane = tid & 31;
    const int g = lane >> 2, t = lane & 3;
    const int wm = (wid & 1) * 64;
    const int wn = (wid >> 1) * 32;
    const int n0 = blockIdx.x * BN;
    const int m0 = blockIdx.y * BM;

    const int8_t* gA = g_q + (size_t)m0 * KDIM;
    const int8_t* gB = g_w + (size_t)n0 * KDIM;

    auto load_stage = [&](int s, int kt) {
        const uint32_t sa = sbase + s * STAGE_BYTES;
        const uint32_t sb = sa + TILE_BYTES;
        const int kb = kt * BK;
#pragma unroll
        for (int it = 0; it < 2; it++) {
            int c = tid + it * 256;              // 512 chunks for A
            int row = c >> 2, col = c & 3;
            cp_async16(sa + row * PITCH + col * 16,
                       gA + (size_t)row * KDIM + kb + col * 16);
        }
#pragma unroll
        for (int it = 0; it < 2; it++) {
            int c = tid + it * 256;              // 512 chunks for B
            int row = c >> 2, col = c & 3;
            cp_async16(sb + row * PITCH + col * 16,
                       gB + (size_t)row * KDIM + kb + col * 16);
        }
    };

    int acc[4][4][4];
#pragma unroll
    for (int mi = 0; mi < 4; mi++)
#pragma unroll
        for (int ni = 0; ni < 4; ni++)
#pragma unroll
            for (int r = 0; r < 4; r++) acc[mi][ni][r] = 0;

    // ldmatrix lane address components (R2-verified mapping)
    const int a_row  = wm + (lane & 15);
    const int a_col16 = (lane >> 4) << 4;                    // 0 or 16
    const int b_row  = wn + (lane & 7) + ((lane >> 4) << 3); // n-row
    const int b_col16 = (lane & 8) * 2;                      // 0 or 16

    load_stage(0, 0); cp_commit();
    load_stage(1, 1); cp_commit();

#pragma unroll 1
    for (int kt = 0; kt < KTILES; kt++) {
        if (kt + 2 < KTILES) load_stage((kt + 2) % NSTAGE, kt + 2);
        cp_commit();
        cp_wait<2>();
        __syncthreads();

        const uint32_t sa = sbase + (kt % NSTAGE) * STAGE_BYTES;
        const uint32_t sb = sa + TILE_BYTES;

#pragma unroll
        for (int c = 0; c < 2; c++) {                 // two k32 chunks per ktile
            uint32_t afr[4][4];
#pragma unroll
            for (int mi = 0; mi < 4; mi++)
                ldsm_x4(afr[mi], sa + (a_row + mi * 16) * PITCH + c * 32 + a_col16);
            uint32_t bfr[4][2];
#pragma unroll
            for (int p = 0; p < 2; p++) {
                uint32_t r4[4];
                ldsm_x4(r4, sb + (b_row + p * 16) * PITCH + c * 32 + b_col16);
                bfr[2 * p][0] = r4[0]; bfr[2 * p][1] = r4[1];
                bfr[2 * p + 1][0] = r4[2]; bfr[2 * p + 1][1] = r4[3];
            }
#pragma unroll
            for (int mi = 0; mi < 4; mi++)
#pragma unroll
                for (int ni = 0; ni < 4; ni++)
                    mma_s8(acc[mi][ni], afr[mi], bfr[ni]);
        }
        __syncthreads();
    }

    // ---- epilogue: out = acc * (A_SCALE*W_SCALE) + bias, FP32 ----
    const float SCALE = 5.0e-4f;
#pragma unroll
    for (int mi = 0; mi < 4; mi++) {
        const int row = m0 + wm + mi * 16 + g;
        float* p0 = out + (size_t)row * NDIM + n0 + wn;
        float* p1 = p0 + (size_t)8 * NDIM;
#pragma unroll
        for (int ni = 0; ni < 4; ni++) {
            const int* cc = acc[mi][ni];
            const int coff = ni * 8 + t * 2;
            float b0 = bias[n0 + wn + coff];
            float b1 = bias[n0 + wn + coff + 1];
            float2 v01, v23;
            v01.x = __fadd_rn(__fmul_rn((float)cc[0], SCALE), b0);
            v01.y = __fadd_rn(__fmul_rn((float)cc[1], SCALE), b1);
            v23.x = __fadd_rn(__fmul_rn((float)cc[2], SCALE), b0);
            v23.y = __fadd_rn(__fmul_rn((float)cc[3], SCALE), b1);
            *(float2*)(p0 + coff) = v01;
            *(float2*)(p1 + coff) = v23;
        }
    }
}

// ===================== launch =====================
extern "C" void kernel_launch(void* const* d_in, const int* in_sizes, int n_in,
                              void* d_out, int out_size) {
    const float* x    = nullptr;
    const int*   wp   = nullptr;
    const float* bias = nullptr;
    for (int i = 0; i < n_in; i++) {
        if (in_sizes[i] == MROWS * KDIM)            x    = (const float*)d_in[i];
        else if (in_sizes[i] == NDIM * KDIM / 2)    wp   = (const int*)d_in[i];
        else if (in_sizes[i] == NDIM)               bias = (const float*)d_in[i];
    }
    if (x == nullptr)    x    = (const float*)d_in[0];
    if (wp == nullptr)   wp   = (const int*)d_in[1];
    if (bias == nullptr) bias = (const float*)d_in[2];
    float* out = (float*)d_out;

    quant_kernel<<<(MROWS * KDIM / 16 + 255) / 256, 256>>>(x);
    unpack_kernel<<<(NDIM * KDIM / 8 + 255) / 256, 256>>>((const int4*)wp);

    cudaFuncSetAttribute(gemm_kernel, cudaFuncAttributeMaxDynamicSharedMemorySize, SMEM_BYTES);
    dim3 grid(NDIM / BN, MROWS / BM);   // (8, 256)
    gemm_kernel<<<grid, 256, SMEM_BYTES>>>(bias, out);
}

// round 13
// speedup vs baseline: 1.2528x; 1.0833x over previous
#include <cuda_runtime.h>
#include <cuda_bf16.h>
#include <cstdint>

// ===================== problem constants =====================
static constexpr int MROWS = 32768;
static constexpr int KDIM  = 1024;
static constexpr int NDIM  = 1024;

// ===================== IMMA GEMM tiling (unchanged, known-good) =====================
static constexpr int BM = 128;
static constexpr int BN = 128;
static constexpr int BK = 64;
static constexpr int KTILES = KDIM / BK;      // 16
static constexpr int NSTAGE = 3;
static constexpr int PITCH = 80;
static constexpr int TILE_BYTES = 128 * PITCH;
static constexpr int STAGE_BYTES = 2 * TILE_BYTES;
static constexpr int SMEM_BYTES = NSTAGE * STAGE_BYTES; // 61440

// ===================== HMMA (bf16) tiling =====================
static constexpr int HPITCH = 144;            // 128B data + 16B pad
static constexpr int HTILE = 128 * HPITCH;    // 18432
static constexpr int HSTAGE_BYTES = 2 * HTILE;
static constexpr int HNSTAGE = 2;
static constexpr int HSMEM_BYTES = HNSTAGE * HSTAGE_BYTES; // 73728

// split: cols [0, NSPLIT) -> IMMA, [NSPLIT, NDIM) -> HMMA
static constexpr int NSPLIT = 768;

// ===================== scratch =====================
__device__ __align__(16) int8_t        g_q [(size_t)MROWS * KDIM];   // int8 acts (32MB)
__device__ __align__(16) int8_t        g_w [(size_t)NDIM * KDIM];    // int8 weights (1MB)
__device__ __align__(16) __nv_bfloat16 g_qh[(size_t)MROWS * KDIM];   // bf16 acts (64MB)
__device__ __align__(16) __nv_bfloat16 g_wh[(size_t)NDIM * KDIM];    // bf16 weights (2MB)

// ===================== helpers =====================
__device__ __forceinline__ uint32_t smem_u32(const void* p) {
    uint32_t a;
    asm("{ .reg .u64 t; cvta.to.shared.u64 t, %1; cvt.u32.u64 %0, t; }" : "=r"(a) : "l"(p));
    return a;
}
__device__ __forceinline__ void cp_async16(uint32_t dst, const void* src) {
    asm volatile("cp.async.cg.shared.global [%0], [%1], 16;" :: "r"(dst), "l"(src) : "memory");
}
__device__ __forceinline__ void cp_commit() {
    asm volatile("cp.async.commit_group;" ::: "memory");
}
template <int N>
__device__ __forceinline__ void cp_wait() {
    asm volatile("cp.async.wait_group %0;" :: "n"(N) : "memory");
}
__device__ __forceinline__ void ldsm_x4(uint32_t* r, uint32_t addr) {
    asm volatile("ldmatrix.sync.aligned.m8n8.x4.shared.b16 {%0,%1,%2,%3}, [%4];"
                 : "=r"(r[0]), "=r"(r[1]), "=r"(r[2]), "=r"(r[3]) : "r"(addr));
}
__device__ __forceinline__ void mma_s8(int* d, const uint32_t* a, const uint32_t* b) {
    asm volatile(
        "mma.sync.aligned.m16n8k32.row.col.s32.s8.s8.s32 "
        "{%0,%1,%2,%3}, {%4,%5,%6,%7}, {%8,%9}, {%0,%1,%2,%3};"
        : "+r"(d[0]), "+r"(d[1]), "+r"(d[2]), "+r"(d[3])
        : "r"(a[0]), "r"(a[1]), "r"(a[2]), "r"(a[3]), "r"(b[0]), "r"(b[1]));
}
__device__ __forceinline__ void mma_bf16(float* d, const uint32_t* a, const uint32_t* b) {
    asm volatile(
        "mma.sync.aligned.m16n8k16.row.col.f32.bf16.bf16.f32 "
        "{%0,%1,%2,%3}, {%4,%5,%6,%7}, {%8,%9}, {%0,%1,%2,%3};"
        : "+f"(d[0]), "+f"(d[1]), "+f"(d[2]), "+f"(d[3])
        : "r"(a[0]), "r"(a[1]), "r"(a[2]), "r"(a[3]), "r"(b[0]), "r"(b[1]));
}

// ===================== pass 1: quantize fp32 -> int8 AND bf16 =====================
__global__ void __launch_bounds__(256) quant_kernel(const float* __restrict__ x) {
    const int i = blockIdx.x * blockDim.x + threadIdx.x;   // one 16-element group
    const int ngroups = (MROWS * KDIM) / 16;
    if (i >= ngroups) return;
    const float4* xv = (const float4*)x + i * 4;
    uint32_t wi[4];
    uint32_t hb[8];
#pragma unroll
    for (int j = 0; j < 4; j++) {
        float4 v = xv[j];
        int q0 = max(-127, min(127, __float2int_rn(__fmul_rn(v.x, 20.0f))));
        int q1 = max(-127, min(127, __float2int_rn(__fmul_rn(v.y, 20.0f))));
        int q2 = max(-127, min(127, __float2int_rn(__fmul_rn(v.z, 20.0f))));
        int q3 = max(-127, min(127, __float2int_rn(__fmul_rn(v.w, 20.0f))));
        wi[j] = (uint32_t)(q0 & 0xFF) | ((uint32_t)(q1 & 0xFF) << 8) |
                ((uint32_t)(q2 & 0xFF) << 16) | ((uint32_t)(q3 & 0xFF) << 24);
        __nv_bfloat162 p01 = __floats2bfloat162_rn((float)q0, (float)q1);
        __nv_bfloat162 p23 = __floats2bfloat162_rn((float)q2, (float)q3);
        hb[2 * j]     = *(uint32_t*)&p01;
        hb[2 * j + 1] = *(uint32_t*)&p23;
    }
    uint4 st; st.x = wi[0]; st.y = wi[1]; st.z = wi[2]; st.w = wi[3];
    ((uint4*)g_q)[i] = st;
    uint4 h0; h0.x = hb[0]; h0.y = hb[1]; h0.z = hb[2]; h0.w = hb[3];
    uint4 h1; h1.x = hb[4]; h1.y = hb[5]; h1.z = hb[6]; h1.w = hb[7];
    ((uint4*)g_qh)[i * 2]     = h0;
    ((uint4*)g_qh)[i * 2 + 1] = h1;
}

// ===================== pass 1b: unpack int4 -> int8 AND bf16 =====================
__global__ void __launch_bounds__(256) unpack_kernel(const int4* __restrict__ wp) {
    int i = blockIdx.x * blockDim.x + threadIdx.x;   // one int4 = 4 packed bytes = 8 weights
    if (i >= (NDIM * KDIM) / 8) return;
    int4 e = wp[i];
    int b[4] = {e.x & 0xFF, e.y & 0xFF, e.z & 0xFF, e.w & 0xFF};
    int v[8];
#pragma unroll
    for (int j = 0; j < 4; j++) {
        int lo = (b[j] & 0xF);        lo -= (lo >= 8) ? 16 : 0;
        int hi = (b[j] >> 4) & 0xF;   hi -= (hi >= 8) ? 16 : 0;
        v[2 * j] = lo; v[2 * j + 1] = hi;
    }
    uint2 st;
    st.x = (uint32_t)(v[0] & 0xFF) | ((uint32_t)(v[1] & 0xFF) << 8) |
           ((uint32_t)(v[2] & 0xFF) << 16) | ((uint32_t)(v[3] & 0xFF) << 24);
    st.y = (uint32_t)(v[4] & 0xFF) | ((uint32_t)(v[5] & 0xFF) << 8) |
           ((uint32_t)(v[6] & 0xFF) << 16) | ((uint32_t)(v[7] & 0xFF) << 24);
    ((uint2*)g_w)[i] = st;
    uint4 h;
    uint32_t* hw = (uint32_t*)&h;
#pragma unroll
    for (int j = 0; j < 4; j++) {
        __nv_bfloat162 p = __floats2bfloat162_rn((float)v[2 * j], (float)v[2 * j + 1]);
        hw[j] = *(uint32_t*)&p;
    }
    ((uint4*)g_wh)[i] = h;
}

// ===================== pass 2a: IMMA GEMM (unchanged), cols [0, NSPLIT) =====================
__global__ void __launch_bounds__(256, 2)
gemm_imma(const float* __restrict__ bias, float* __restrict__ out) {
    extern __shared__ char smem[];
    const uint32_t sbase = smem_u32(smem);
    const int tid  = threadIdx.x;
    const int wid  = tid >> 5;
    const int lane = tid & 31;
    const int g = lane >> 2, t = lane & 3;
    const int wm = (wid & 1) * 64;
    const int wn = (wid >> 1) * 32;
    const int n0 = blockIdx.x * BN;
    const int m0 = blockIdx.y * BM;

    const int8_t* gA = g_q + (size_t)m0 * KDIM;
    const int8_t* gB = g_w + (size_t)n0 * KDIM;

    auto load_stage = [&](int s, int kt) {
        const uint32_t sa = sbase + s * STAGE_BYTES;
        const uint32_t sb = sa + TILE_BYTES;
        const int kb = kt * BK;
#pragma unroll
        for (int it = 0; it < 2; it++) {
            int c = tid + it * 256;
            int row = c >> 2, col = c & 3;
            cp_async16(sa + row * PITCH + col * 16,
                       gA + (size_t)row * KDIM + kb + col * 16);
        }
#pragma unroll
        for (int it = 0; it < 2; it++) {
            int c = tid + it * 256;
            int row = c >> 2, col = c & 3;
            cp_async16(sb + row * PITCH + col * 16,
                       gB + (size_t)row * KDIM + kb + col * 16);
        }
    };

    int acc[4][4][4];
#pragma unroll
    for (int mi = 0; mi < 4; mi++)
#pragma unroll
        for (int ni = 0; ni < 4; ni++)
#pragma unroll
            for (int r = 0; r < 4; r++) acc[mi][ni][r] = 0;

    const int a_row  = wm + (lane & 15);
    const int a_col16 = (lane >> 4) << 4;
    const int b_row  = wn + (lane & 7) + ((lane >> 4) << 3);
    const int b_col16 = (lane & 8) * 2;

    load_stage(0, 0); cp_commit();
    load_stage(1, 1); cp_commit();

#pragma unroll 1
    for (int kt = 0; kt < KTILES; kt++) {
        if (kt + 2 < KTILES) load_stage((kt + 2) % NSTAGE, kt + 2);
        cp_commit();
        cp_wait<2>();
        __syncthreads();

        const uint32_t sa = sbase + (kt % NSTAGE) * STAGE_BYTES;
        const uint32_t sb = sa + TILE_BYTES;

#pragma unroll
        for (int c = 0; c < 2; c++) {
            uint32_t afr[4][4];
#pragma unroll
            for (int mi = 0; mi < 4; mi++)
                ldsm_x4(afr[mi], sa + (a_row + mi * 16) * PITCH + c * 32 + a_col16);
            uint32_t bfr[4][2];
#pragma unroll
            for (int p = 0; p < 2; p++) {
                uint32_t r4[4];
                ldsm_x4(r4, sb + (b_row + p * 16) * PITCH + c * 32 + b_col16);
                bfr[2 * p][0] = r4[0]; bfr[2 * p][1] = r4[1];
                bfr[2 * p + 1][0] = r4[2]; bfr[2 * p + 1][1] = r4[3];
            }
#pragma unroll
            for (int mi = 0; mi < 4; mi++)
#pragma unroll
                for (int ni = 0; ni < 4; ni++)
                    mma_s8(acc[mi][ni], afr[mi], bfr[ni]);
        }
        __syncthreads();
    }

    const float SCALE = 5.0e-4f;
#pragma unroll
    for (int mi = 0; mi < 4; mi++) {
        const int row = m0 + wm + mi * 16 + g;
        float* p0 = out + (size_t)row * NDIM + n0 + wn;
        float* p1 = p0 + (size_t)8 * NDIM;
#pragma unroll
        for (int ni = 0; ni < 4; ni++) {
            const int* cc = acc[mi][ni];
            const int coff = ni * 8 + t * 2;
            float b0 = bias[n0 + wn + coff];
            float b1 = bias[n0 + wn + coff + 1];
            float2 v01, v23;
            v01.x = __fadd_rn(__fmul_rn((float)cc[0], SCALE), b0);
            v01.y = __fadd_rn(__fmul_rn((float)cc[1], SCALE), b1);
            v23.x = __fadd_rn(__fmul_rn((float)cc[2], SCALE), b0);
            v23.y = __fadd_rn(__fmul_rn((float)cc[3], SCALE), b1);
            *(float2*)(p0 + coff) = v01;
            *(float2*)(p1 + coff) = v23;
        }
    }
}

// ===================== pass 2b: HMMA bf16 GEMM, cols [NSPLIT, NDIM) =====================
__global__ void __launch_bounds__(256, 2)
gemm_hmma(const float* __restrict__ bias, float* __restrict__ out) {
    extern __shared__ char smem[];
    const uint32_t sbase = smem_u32(smem);
    const int tid  = threadIdx.x;
    const int wid  = tid >> 5;
    const int lane = tid & 31;
    const int g = lane >> 2, t = lane & 3;
    const int wm = (wid & 1) * 64;
    const int wn = (wid >> 1) * 32;
    const int n0 = NSPLIT + blockIdx.x * BN;
    const int m0 = blockIdx.y * BM;

    const __nv_bfloat16* gA = g_qh + (size_t)m0 * KDIM;
    const __nv_bfloat16* gB = g_wh + (size_t)n0 * KDIM;

    auto load_stage = [&](int s, int kt) {
        const uint32_t sa = sbase + s * HSTAGE_BYTES;
        const uint32_t sb = sa + HTILE;
        const int kb = kt * BK;       // bf16 elements
#pragma unroll
        for (int it = 0; it < 4; it++) {
            int c = tid + it * 256;           // 1024 chunks for A (128 rows x 8)
            int row = c >> 3, col = c & 7;
            cp_async16(sa + row * HPITCH + col * 16,
                       gA + (size_t)row * KDIM + kb + col * 8);
        }
#pragma unroll
        for (int it = 0; it < 4; it++) {
            int c = tid + it * 256;           // 1024 chunks for B
            int row = c >> 3, col = c & 7;
            cp_async16(sb + row * HPITCH + col * 16,
                       gB + (size_t)row * KDIM + kb + col * 8);
        }
    };

    float acc[4][4][4];
#pragma unroll
    for (int mi = 0; mi < 4; mi++)
#pragma unroll
        for (int ni = 0; ni < 4; ni++)
#pragma unroll
            for (int r = 0; r < 4; r++) acc[mi][ni][r] = 0.0f;

    const int a_row  = wm + (lane & 15);
    const int a_col16 = (lane >> 4) << 4;
    const int b_row  = wn + (lane & 7) + ((lane >> 4) << 3);
    const int b_col16 = (lane & 8) * 2;

    load_stage(0, 0); cp_commit();

#pragma unroll 1
    for (int kt = 0; kt < KTILES; kt++) {
        if (kt + 1 < KTILES) load_stage((kt + 1) % HNSTAGE, kt + 1);
        cp_commit();
        cp_wait<1>();
        __syncthreads();

        const uint32_t sa = sbase + (kt % HNSTAGE) * HSTAGE_BYTES;
        const uint32_t sb = sa + HTILE;

#pragma unroll
        for (int c = 0; c < 4; c++) {                 // four k16 chunks per ktile
            uint32_t afr[4][4];
#pragma unroll
            for (int mi = 0; mi < 4; mi++)
                ldsm_x4(afr[mi], sa + (a_row + mi * 16) * HPITCH + c * 32 + a_col16);
            uint32_t bfr[4][2];
#pragma unroll
            for (int p = 0; p < 2; p++) {
                uint32_t r4[4];
                ldsm_x4(r4, sb + (b_row + p * 16) * HPITCH + c * 32 + b_col16);
                bfr[2 * p][0] = r4[0]; bfr[2 * p][1] = r4[1];
                bfr[2 * p + 1][0] = r4[2]; bfr[2 * p + 1][1] = r4[3];
            }
#pragma unroll
            for (int mi = 0; mi < 4; mi++)
#pragma unroll
                for (int ni = 0; ni < 4; ni++)
                    mma_bf16(acc[mi][ni], afr[mi], bfr[ni]);
        }
        __syncthreads();
    }

    const float SCALE = 5.0e-4f;
#pragma unroll
    for (int mi = 0; mi < 4; mi++) {
        const int row = m0 + wm + mi * 16 + g;
        float* p0 = out + (size_t)row * NDIM + n0 + wn;
        float* p1 = p0 + (size_t)8 * NDIM;
#pragma unroll
        for (int ni = 0; ni < 4; ni++) {
            const float* cc = acc[mi][ni];
            const int coff = ni * 8 + t * 2;
            float b0 = bias[n0 + wn + coff];
            float b1 = bias[n0 + wn + coff + 1];
            float2 v01, v23;
            v01.x = __fadd_rn(__fmul_rn(cc[0], SCALE), b0);
            v01.y = __fadd_rn(__fmul_rn(cc[1], SCALE), b1);
            v23.x = __fadd_rn(__fmul_rn(cc[2], SCALE), b0);
            v23.y = __fadd_rn(__fmul_rn(cc[3], SCALE), b1);
            *(float2*)(p0 + coff) = v01;
            *(float2*)(p1 + coff) = v23;
        }
    }
}

// ===================== launch =====================
extern "C" void kernel_launch(void* const* d_in, const int* in_sizes, int n_in,
                              void* d_out, int out_size) {
    const float* x    = nullptr;
    const int*   wp   = nullptr;
    const float* bias = nullptr;
    for (int i = 0; i < n_in; i++) {
        if (in_sizes[i] == MROWS * KDIM)            x    = (const float*)d_in[i];
        else if (in_sizes[i] == NDIM * KDIM / 2)    wp   = (const int*)d_in[i];
        else if (in_sizes[i] == NDIM)               bias = (const float*)d_in[i];
    }
    if (x == nullptr)    x    = (const float*)d_in[0];
    if (wp == nullptr)   wp   = (const int*)d_in[1];
    if (bias == nullptr) bias = (const float*)d_in[2];
    float* out = (float*)d_out;

    quant_kernel<<<(MROWS * KDIM / 16 + 255) / 256, 256>>>(x);
    unpack_kernel<<<(NDIM * KDIM / 8 + 255) / 256, 256>>>((const int4*)wp);

    cudaFuncSetAttribute(gemm_imma, cudaFuncAttributeMaxDynamicSharedMemorySize, SMEM_BYTES);
    cudaFuncSetAttribute(gemm_hmma, cudaFuncAttributeMaxDynamicSharedMemorySize, HSMEM_BYTES);

    dim3 grid_i(NSPLIT / BN, MROWS / BM);            // (6, 256)
    gemm_imma<<<grid_i, 256, SMEM_BYTES>>>(bias, out);
    dim3 grid_h((NDIM - NSPLIT) / BN, MROWS / BM);   // (2, 256)
    gemm_hmma<<<grid_h, 256, HSMEM_BYTES>>>(bias, out);
}

// round 14
// speedup vs baseline: 2.8249x; 2.2549x over previous
#include <cuda_runtime.h>
#include <cuda_bf16.h>
#include <cstdint>

// ===================== problem constants =====================
static constexpr int MROWS = 32768;
static constexpr int KDIM  = 1024;
static constexpr int NDIM  = 1024;

// ===================== HMMA GEMM tiling =====================
static constexpr int BM = 128;
static constexpr int BN = 128;
static constexpr int BK = 64;                 // bf16 k per tile (128 bytes)
static constexpr int KTILES = KDIM / BK;      // 16
static constexpr int NSTAGE = 3;
static constexpr int ROWB = 128;              // bytes per smem row (swizzled, no pad)
static constexpr int TILE_BYTES = 128 * ROWB;           // 16KB per operand
static constexpr int STAGE_BYTES = 2 * TILE_BYTES;      // A + B = 32KB
static constexpr int SMEM_BYTES = NSTAGE * STAGE_BYTES; // 98304

// ===================== scratch =====================
__device__ __align__(16) __nv_bfloat16 g_qh[(size_t)MROWS * KDIM];   // bf16 acts (64MB)
__device__ __align__(16) __nv_bfloat16 g_wh[(size_t)NDIM * KDIM];    // bf16 weights (2MB)

// ===================== helpers =====================
__device__ __forceinline__ uint32_t smem_u32(const void* p) {
    uint32_t a;
    asm("{ .reg .u64 t; cvta.to.shared.u64 t, %1; cvt.u32.u64 %0, t; }" : "=r"(a) : "l"(p));
    return a;
}
__device__ __forceinline__ void cp_async16(uint32_t dst, const void* src) {
    asm volatile("cp.async.cg.shared.global [%0], [%1], 16;" :: "r"(dst), "l"(src) : "memory");
}
__device__ __forceinline__ void cp_commit() {
    asm volatile("cp.async.commit_group;" ::: "memory");
}
template <int N>
__device__ __forceinline__ void cp_wait() {
    asm volatile("cp.async.wait_group %0;" :: "n"(N) : "memory");
}
__device__ __forceinline__ void ldsm_x4(uint32_t* r, uint32_t addr) {
    asm volatile("ldmatrix.sync.aligned.m8n8.x4.shared.b16 {%0,%1,%2,%3}, [%4];"
                 : "=r"(r[0]), "=r"(r[1]), "=r"(r[2]), "=r"(r[3]) : "r"(addr));
}
__device__ __forceinline__ void mma_bf16(float* d, const uint32_t* a, const uint32_t* b) {
    asm volatile(
        "mma.sync.aligned.m16n8k16.row.col.f32.bf16.bf16.f32 "
        "{%0,%1,%2,%3}, {%4,%5,%6,%7}, {%8,%9}, {%0,%1,%2,%3};"
        : "+f"(d[0]), "+f"(d[1]), "+f"(d[2]), "+f"(d[3])
        : "r"(a[0]), "r"(a[1]), "r"(a[2]), "r"(a[3]), "r"(b[0]), "r"(b[1]));
}

// ===================== pass 1: quantize fp32 -> bf16 ints =====================
__global__ void __launch_bounds__(256) quant_kernel(const float* __restrict__ x) {
    const int i = blockIdx.x * blockDim.x + threadIdx.x;   // one 16-element group
    const int ngroups = (MROWS * KDIM) / 16;
    if (i >= ngroups) return;
    const float4* xv = (const float4*)x + i * 4;
    uint32_t hb[8];
#pragma unroll
    for (int j = 0; j < 4; j++) {
        float4 v = xv[j];
        int q0 = max(-127, min(127, __float2int_rn(__fmul_rn(v.x, 20.0f))));
        int q1 = max(-127, min(127, __float2int_rn(__fmul_rn(v.y, 20.0f))));
        int q2 = max(-127, min(127, __float2int_rn(__fmul_rn(v.z, 20.0f))));
        int q3 = max(-127, min(127, __float2int_rn(__fmul_rn(v.w, 20.0f))));
        __nv_bfloat162 p01 = __floats2bfloat162_rn((float)q0, (float)q1);
        __nv_bfloat162 p23 = __floats2bfloat162_rn((float)q2, (float)q3);
        hb[2 * j]     = *(uint32_t*)&p01;
        hb[2 * j + 1] = *(uint32_t*)&p23;
    }
    uint4 h0; h0.x = hb[0]; h0.y = hb[1]; h0.z = hb[2]; h0.w = hb[3];
    uint4 h1; h1.x = hb[4]; h1.y = hb[5]; h1.z = hb[6]; h1.w = hb[7];
    ((uint4*)g_qh)[i * 2]     = h0;
    ((uint4*)g_qh)[i * 2 + 1] = h1;
}

// ===================== pass 1b: unpack int4 -> bf16 =====================
// weight_packed delivered as int32 elements (uint8 widened by harness).
__global__ void __launch_bounds__(256) unpack_kernel(const int4* __restrict__ wp) {
    int i = blockIdx.x * blockDim.x + threadIdx.x;   // one int4 = 4 packed bytes = 8 weights
    if (i >= (NDIM * KDIM) / 8) return;
    int4 e = wp[i];
    int b[4] = {e.x & 0xFF, e.y & 0xFF, e.z & 0xFF, e.w & 0xFF};
    uint4 h;
    uint32_t* hw = (uint32_t*)&h;
#pragma unroll
    for (int j = 0; j < 4; j++) {
        int lo = (b[j] & 0xF);        lo -= (lo >= 8) ? 16 : 0;
        int hi = (b[j] >> 4) & 0xF;   hi -= (hi >= 8) ? 16 : 0;
        __nv_bfloat162 p = __floats2bfloat162_rn((float)lo, (float)hi);
        hw[j] = *(uint32_t*)&p;
    }
    ((uint4*)g_wh)[i] = h;
}

// ===================== pass 2: HMMA bf16 GEMM, swizzled smem, 3 stages =====================
// CTA: 256 threads = 8 warps in 2(m) x 4(n); warp tile 64x32.
__global__ void __launch_bounds__(256, 2)
gemm_hmma(const float* __restrict__ bias, float* __restrict__ out) {
    extern __shared__ char smem[];
    const uint32_t sbase = smem_u32(smem);
    const int tid  = threadIdx.x;
    const int wid  = tid >> 5;
    const int lane = tid & 31;
    const int g = lane >> 2, t = lane & 3;
    const int wm = (wid & 1) * 64;
    const int wn = (wid >> 1) * 32;
    const int n0 = blockIdx.x * BN;
    const int m0 = blockIdx.y * BM;

    const __nv_bfloat16* gA = g_qh + (size_t)m0 * KDIM;
    const __nv_bfloat16* gB = g_wh + (size_t)n0 * KDIM;

    // swizzled store: row r, 16B-chunk c -> offset r*128 + (c ^ (r&7))*16
    auto load_stage = [&](int s, int kt) {
        const uint32_t sa = sbase + s * STAGE_BYTES;
        const uint32_t sb = sa + TILE_BYTES;
        const int kb = kt * BK;       // bf16 elements
#pragma unroll
        for (int it = 0; it < 4; it++) {
            int c = tid + it * 256;           // 1024 chunks for A
            int row = c >> 3, col = c & 7;
            int scol = col ^ (row & 7);
            cp_async16(sa + row * ROWB + scol * 16,
                       gA + (size_t)row * KDIM + kb + col * 8);
        }
#pragma unroll
        for (int it = 0; it < 4; it++) {
            int c = tid + it * 256;           // 1024 chunks for B
            int row = c >> 3, col = c & 7;
            int scol = col ^ (row & 7);
            cp_async16(sb + row * ROWB + scol * 16,
                       gB + (size_t)row * KDIM + kb + col * 8);
        }
    };

    float acc[4][4][4];
#pragma unroll
    for (int mi = 0; mi < 4; mi++)
#pragma unroll
        for (int ni = 0; ni < 4; ni++)
#pragma unroll
            for (int r = 0; r < 4; r++) acc[mi][ni][r] = 0.0f;

    // ldmatrix lane -> logical (row, chunk): A row = wm + (lane&15), chunk base = lane>>4
    const int a_row   = wm + (lane & 15);
    const int a_chunk = lane >> 4;                              // 0 or 1
    const int b_row   = wn + (lane & 7) + ((lane >> 4) << 3);
    const int b_chunk = (lane >> 3) & 1;                        // 0 or 1

    load_stage(0, 0); cp_commit();
    load_stage(1, 1); cp_commit();

#pragma unroll 1
    for (int kt = 0; kt < KTILES; kt++) {
        if (kt + 2 < KTILES) load_stage((kt + 2) % NSTAGE, kt + 2);
        cp_commit();
        cp_wait<2>();
        __syncthreads();

        const uint32_t sa = sbase + (kt % NSTAGE) * STAGE_BYTES;
        const uint32_t sb = sa + TILE_BYTES;

#pragma unroll
        for (int c = 0; c < 4; c++) {                 // four k16 chunks per ktile
            uint32_t afr[4][4];
#pragma unroll
            for (int mi = 0; mi < 4; mi++) {
                int r = a_row + mi * 16;
                int ch = (2 * c + a_chunk) ^ (r & 7);
                ldsm_x4(afr[mi], sa + r * ROWB + ch * 16);
            }
            uint32_t bfr[4][2];
#pragma unroll
            for (int p = 0; p < 2; p++) {
                int r = b_row + p * 16;
                int ch = (2 * c + b_chunk) ^ (r & 7);
                uint32_t r4[4];
                ldsm_x4(r4, sb + r * ROWB + ch * 16);
                bfr[2 * p][0] = r4[0]; bfr[2 * p][1] = r4[1];
                bfr[2 * p + 1][0] = r4[2]; bfr[2 * p + 1][1] = r4[3];
            }
#pragma unroll
            for (int mi = 0; mi < 4; mi++)
#pragma unroll
                for (int ni = 0; ni < 4; ni++)
                    mma_bf16(acc[mi][ni], afr[mi], bfr[ni]);
        }
        __syncthreads();
    }

    // ---- epilogue: out = acc * (A_SCALE*W_SCALE) + bias, FP32 ----
    const float SCALE = 5.0e-4f;
#pragma unroll
    for (int mi = 0; mi < 4; mi++) {
        const int row = m0 + wm + mi * 16 + g;
        float* p0 = out + (size_t)row * NDIM + n0 + wn;
        float* p1 = p0 + (size_t)8 * NDIM;
#pragma unroll
        for (int ni = 0; ni < 4; ni++) {
            const float* cc = acc[mi][ni];
            const int coff = ni * 8 + t * 2;
            float b0 = bias[n0 + wn + coff];
            float b1 = bias[n0 + wn + coff + 1];
            float2 v01, v23;
            v01.x = __fadd_rn(__fmul_rn(cc[0], SCALE), b0);
            v01.y = __fadd_rn(__fmul_rn(cc[1], SCALE), b1);
            v23.x = __fadd_rn(__fmul_rn(cc[2], SCALE), b0);
            v23.y = __fadd_rn(__fmul_rn(cc[3], SCALE), b1);
            *(float2*)(p0 + coff) = v01;
            *(float2*)(p1 + coff) = v23;
        }
    }
}

// ===================== launch =====================
extern "C" void kernel_launch(void* const* d_in, const int* in_sizes, int n_in,
                              void* d_out, int out_size) {
    const float* x    = nullptr;
    const int*   wp   = nullptr;
    const float* bias = nullptr;
    for (int i = 0; i < n_in; i++) {
        if (in_sizes[i] == MROWS * KDIM)            x    = (const float*)d_in[i];
        else if (in_sizes[i] == NDIM * KDIM / 2)    wp   = (const int*)d_in[i];
        else if (in_sizes[i] == NDIM)               bias = (const float*)d_in[i];
    }
    if (x == nullptr)    x    = (const float*)d_in[0];
    if (wp == nullptr)   wp   = (const int*)d_in[1];
    if (bias == nullptr) bias = (const float*)d_in[2];
    float* out = (float*)d_out;

    quant_kernel<<<(MROWS * KDIM / 16 + 255) / 256, 256>>>(x);
    unpack_kernel<<<(NDIM * KDIM / 8 + 255) / 256, 256>>>((const int4*)wp);

    cudaFuncSetAttribute(gemm_hmma, cudaFuncAttributeMaxDynamicSharedMemorySize, SMEM_BYTES);
    dim3 grid(NDIM / BN, MROWS / BM);   // (8, 256)
    gemm_hmma<<<grid, 256, SMEM_BYTES>>>(bias, out);
}